// round 7
// baseline (speedup 1.0000x reference)
#include <cuda_runtime.h>
#include <cuda_bf16.h>
#include <cstdint>

// Problem constants
// B=8, C=256, IC=128, H=W=64, N=4096, M=1024
#define NB   8
#define NC   256
#define NIC  128
#define NPIX 4096   // H*W
#define NM   1024   // pooled pixels
#define MP1  1025

// ---------------- device scratch (no allocations allowed) ----------------
__device__ float g_Wstack[256 * 256];      // rows 0..127 = g_w, 128..255 = phi_w
__device__ float g_bstack[256];
__device__ float g_vt[256];                // theta_w^T w_t
__device__ float g_ct[1];                  // w_t . theta_b
__device__ float g_gpool[NB * NIC * NM];   // pooled g conv      (4 MB)
__device__ float g_sp[NB * NM];
__device__ float g_sp_sorted[NB * NM];
__device__ int   g_perm[NB * NM];
__device__ float g_st[NB * NPIX];
__device__ int   g_kidx[NB * NPIX];
__device__ float g_h[NB * NC * NM];        // W_w @ g_pool       (8 MB)
__device__ float g_A1[NB * NC * MP1];      // suffix sum of h (sorted order)
__device__ float g_A2[NB * NC * MP1];      // suffix sum of sp*h
__device__ float g_scale[256];
__device__ float g_shift[256];

// ---------------- K0: build stacked weights, vt, ct ----------------
__global__ void k_prep(const float* __restrict__ g_w, const float* __restrict__ g_b,
                       const float* __restrict__ phi_w, const float* __restrict__ phi_b,
                       const float* __restrict__ theta_w, const float* __restrict__ theta_b,
                       const float* __restrict__ cp_w) {
    int idx = blockIdx.x * 256 + threadIdx.x;   // grid 256 -> 65536 elems
    int r = idx >> 8, c = idx & 255;
    g_Wstack[idx] = (r < 128) ? g_w[r * 256 + c] : phi_w[(r - 128) * 256 + c];
    if (blockIdx.x == 0) {
        int t = threadIdx.x;
        g_bstack[t] = (t < 128) ? g_b[t] : phi_b[t - 128];
        float acc = 0.f;
        #pragma unroll 4
        for (int ic = 0; ic < 128; ic++) acc += cp_w[ic] * theta_w[ic * 256 + t];
        g_vt[t] = acc;
        if (t == 0) {
            float ct = 0.f;
            for (int ic = 0; ic < 128; ic++) ct += cp_w[ic] * theta_b[ic];
            g_ct[0] = ct;
        }
    }
}

// ---------------- K1: stacked conv (g+phi) GEMM with fused maxpool epilogue ----
// Per batch: Out[256, 4096] = Wstack[256,256] @ x[256,4096].
// Col tile t (128 cols) == image rows 2t,2t+1 == exactly pooled row t.
__global__ __launch_bounds__(256) void k_conv_gp(const float* __restrict__ x,
                                                 const float* __restrict__ cp_w) {
    const int t  = blockIdx.x;   // 0..31 col tile (pooled row)
    const int rt = blockIdx.y;   // 0: g rows, 1: phi rows
    const int b  = blockIdx.z;
    __shared__ float As[2][16][128];
    __shared__ float Bs[2][16][128];
    __shared__ float red[512];
    const int tid = threadIdx.x;
    const int tx = tid & 15, ty = tid >> 4;
    const float* Wb = g_Wstack + rt * 128 * 256;
    const float* xb = x + (size_t)b * 256 * 4096 + t * 128;

    float acc[8][8];
    #pragma unroll
    for (int i = 0; i < 8; i++)
        #pragma unroll
        for (int j = 0; j < 8; j++) acc[i][j] = 0.f;

    // prologue: load k-step 0
    #pragma unroll
    for (int r = 0; r < 2; r++) {
        int id = tid + r * 256;
        int m = id >> 2, kq = id & 3;
        float4 v = *(const float4*)(Wb + m * 256 + kq * 4);
        As[0][kq * 4 + 0][m] = v.x; As[0][kq * 4 + 1][m] = v.y;
        As[0][kq * 4 + 2][m] = v.z; As[0][kq * 4 + 3][m] = v.w;
        int kb = id >> 5, nq = id & 31;
        *(float4*)&Bs[0][kb][nq * 4] = *(const float4*)(xb + (size_t)kb * 4096 + nq * 4);
    }
    __syncthreads();

    #pragma unroll 1
    for (int ks = 0; ks < 16; ks++) {
        int buf = ks & 1;
        if (ks < 15) {
            int k0 = (ks + 1) * 16;
            #pragma unroll
            for (int r = 0; r < 2; r++) {
                int id = tid + r * 256;
                int m = id >> 2, kq = id & 3;
                float4 v = *(const float4*)(Wb + m * 256 + k0 + kq * 4);
                As[buf ^ 1][kq * 4 + 0][m] = v.x; As[buf ^ 1][kq * 4 + 1][m] = v.y;
                As[buf ^ 1][kq * 4 + 2][m] = v.z; As[buf ^ 1][kq * 4 + 3][m] = v.w;
                int kb = id >> 5, nq = id & 31;
                *(float4*)&Bs[buf ^ 1][kb][nq * 4] =
                    *(const float4*)(xb + (size_t)(k0 + kb) * 4096 + nq * 4);
            }
        }
        #pragma unroll
        for (int kk = 0; kk < 16; kk++) {
            float a[8], bb[8];
            *(float4*)&a[0]  = *(const float4*)&As[buf][kk][ty * 8];
            *(float4*)&a[4]  = *(const float4*)&As[buf][kk][ty * 8 + 4];
            *(float4*)&bb[0] = *(const float4*)&Bs[buf][kk][tx * 8];
            *(float4*)&bb[4] = *(const float4*)&Bs[buf][kk][tx * 8 + 4];
            #pragma unroll
            for (int i = 0; i < 8; i++)
                #pragma unroll
                for (int j = 0; j < 8; j++) acc[i][j] += a[i] * bb[j];
        }
        __syncthreads();
    }

    // epilogue: 2x2 maxpool. Thread covers rows ty*8..+7, cols tx*8..+7.
    // Horizontal pair inside thread; vertical (col+64) partner is lane tx+8 (same warp).
    float bias[8];
    #pragma unroll
    for (int i = 0; i < 8; i++) bias[i] = g_bstack[rt * 128 + ty * 8 + i];

    if (rt == 0) {
        #pragma unroll
        for (int i = 0; i < 8; i++) {
            #pragma unroll
            for (int q = 0; q < 4; q++) {
                float hp = fmaxf(acc[i][2 * q], acc[i][2 * q + 1]);
                float other = __shfl_down_sync(0xffffffffu, hp, 8);
                if (tx < 8) {
                    float p = fmaxf(hp, other) + bias[i];
                    int ic = ty * 8 + i;
                    int mw = tx * 4 + q;
                    g_gpool[((size_t)(b * 128 + ic) << 10) + t * 32 + mw] = p;
                }
            }
        }
    } else {
        float wp[8];
        #pragma unroll
        for (int i = 0; i < 8; i++) wp[i] = cp_w[128 + ty * 8 + i];
        float part[4] = {0.f, 0.f, 0.f, 0.f};
        #pragma unroll
        for (int i = 0; i < 8; i++) {
            #pragma unroll
            for (int q = 0; q < 4; q++) {
                float hp = fmaxf(acc[i][2 * q], acc[i][2 * q + 1]);
                float other = __shfl_down_sync(0xffffffffu, hp, 8);
                float p = fmaxf(hp, other) + bias[i];
                part[q] += wp[i] * p;
            }
        }
        if (tx < 8) {
            #pragma unroll
            for (int q = 0; q < 4; q++) red[ty * 32 + tx * 4 + q] = part[q];
        }
        __syncthreads();
        if (tid < 32) {
            float s = 0.f;
            #pragma unroll
            for (int yy = 0; yy < 16; yy++) s += red[yy * 32 + tid];
            g_sp[b * 1024 + t * 32 + tid] = s;
        }
    }
}

// ---------------- K2: s_t[b,n] = vt . x[b,:,n] + ct ----------------
__global__ __launch_bounds__(256) void k_st(const float* __restrict__ x) {
    __shared__ float vts[256];
    int tid = threadIdx.x;
    vts[tid] = g_vt[tid];
    __syncthreads();
    int b = blockIdx.y;
    int n = blockIdx.x * 256 + tid;
    const float* xb = x + (size_t)b * 256 * 4096 + n;
    float a0 = 0.f, a1 = 0.f, a2 = 0.f, a3 = 0.f;
    #pragma unroll 4
    for (int c = 0; c < 256; c += 4) {
        a0 += vts[c + 0] * xb[(size_t)(c + 0) * 4096];
        a1 += vts[c + 1] * xb[(size_t)(c + 1) * 4096];
        a2 += vts[c + 2] * xb[(size_t)(c + 2) * 4096];
        a3 += vts[c + 3] * xb[(size_t)(c + 3) * 4096];
    }
    g_st[b * 4096 + n] = (a0 + a1) + (a2 + a3) + g_ct[0];
}

// ---------------- K3a: bitonic sort s_p (ascending) per batch ----------------
__global__ __launch_bounds__(1024) void k_sort(void) {
    __shared__ float key[1024];
    __shared__ int   idx[1024];
    int b = blockIdx.x, tid = threadIdx.x;
    key[tid] = g_sp[b * 1024 + tid];
    idx[tid] = tid;
    __syncthreads();
    for (int k = 2; k <= 1024; k <<= 1) {
        for (int j = k >> 1; j > 0; j >>= 1) {
            int ixj = tid ^ j;
            if (ixj > tid) {
                bool up = ((tid & k) == 0);
                float a = key[tid], bb = key[ixj];
                bool sw = up ? (a > bb) : (a < bb);
                if (sw) {
                    key[tid] = bb; key[ixj] = a;
                    int ti = idx[tid]; idx[tid] = idx[ixj]; idx[ixj] = ti;
                }
            }
            __syncthreads();
        }
    }
    g_sp_sorted[b * 1024 + tid] = key[tid];
    g_perm[b * 1024 + tid] = idx[tid];
}

// ---------------- K3c: k(b,n) = count of sorted sp <= -s_t ----------------
__global__ __launch_bounds__(512) void k_kidx(void) {
    __shared__ float sp[1024];
    int b = blockIdx.y, tid = threadIdx.x;
    for (int i = tid; i < 1024; i += 512) sp[i] = g_sp_sorted[b * 1024 + i];
    __syncthreads();
    int n = blockIdx.x * 512 + tid;
    float tv = -g_st[b * 4096 + n];
    int lo = 0, hi = 1024;
    #pragma unroll
    for (int it = 0; it < 10; it++) {
        int mid = (lo + hi) >> 1;
        if (sp[mid] <= tv) lo = mid + 1; else hi = mid;
    }
    g_kidx[b * 4096 + n] = lo;
}

// ---------------- K4: h = W_w[256,128] @ g_pool[128,1024] per batch ----------
__global__ __launch_bounds__(256) void k_wgemm(const float* __restrict__ W_w) {
    const int t  = blockIdx.x;   // 0..7 col tile
    const int rt = blockIdx.y;   // 0..1 row tile
    const int b  = blockIdx.z;
    __shared__ float As[2][16][128];
    __shared__ float Bs[2][16][128];
    const int tid = threadIdx.x;
    const int tx = tid & 15, ty = tid >> 4;
    const float* Aw = W_w + rt * 128 * 128;
    const float* Bg = g_gpool + (size_t)b * 128 * 1024 + t * 128;

    float acc[8][8];
    #pragma unroll
    for (int i = 0; i < 8; i++)
        #pragma unroll
        for (int j = 0; j < 8; j++) acc[i][j] = 0.f;

    #pragma unroll
    for (int r = 0; r < 2; r++) {
        int id = tid + r * 256;
        int m = id >> 2, kq = id & 3;
        float4 v = *(const float4*)(Aw + m * 128 + kq * 4);
        As[0][kq * 4 + 0][m] = v.x; As[0][kq * 4 + 1][m] = v.y;
        As[0][kq * 4 + 2][m] = v.z; As[0][kq * 4 + 3][m] = v.w;
        int kb = id >> 5, nq = id & 31;
        *(float4*)&Bs[0][kb][nq * 4] = *(const float4*)(Bg + (size_t)kb * 1024 + nq * 4);
    }
    __syncthreads();

    #pragma unroll 1
    for (int ks = 0; ks < 8; ks++) {
        int buf = ks & 1;
        if (ks < 7) {
            int k0 = (ks + 1) * 16;
            #pragma unroll
            for (int r = 0; r < 2; r++) {
                int id = tid + r * 256;
                int m = id >> 2, kq = id & 3;
                float4 v = *(const float4*)(Aw + m * 128 + k0 + kq * 4);
                As[buf ^ 1][kq * 4 + 0][m] = v.x; As[buf ^ 1][kq * 4 + 1][m] = v.y;
                As[buf ^ 1][kq * 4 + 2][m] = v.z; As[buf ^ 1][kq * 4 + 3][m] = v.w;
                int kb = id >> 5, nq = id & 31;
                *(float4*)&Bs[buf ^ 1][kb][nq * 4] =
                    *(const float4*)(Bg + (size_t)(k0 + kb) * 1024 + nq * 4);
            }
        }
        #pragma unroll
        for (int kk = 0; kk < 16; kk++) {
            float a[8], bb[8];
            *(float4*)&a[0]  = *(const float4*)&As[buf][kk][ty * 8];
            *(float4*)&a[4]  = *(const float4*)&As[buf][kk][ty * 8 + 4];
            *(float4*)&bb[0] = *(const float4*)&Bs[buf][kk][tx * 8];
            *(float4*)&bb[4] = *(const float4*)&Bs[buf][kk][tx * 8 + 4];
            #pragma unroll
            for (int i = 0; i < 8; i++)
                #pragma unroll
                for (int j = 0; j < 8; j++) acc[i][j] += a[i] * bb[j];
        }
        __syncthreads();
    }

    #pragma unroll
    for (int i = 0; i < 8; i++) {
        size_t ro = ((size_t)(b * 256 + rt * 128 + ty * 8 + i) << 10) + t * 128 + tx * 8;
        *(float4*)&g_h[ro]     = make_float4(acc[i][0], acc[i][1], acc[i][2], acc[i][3]);
        *(float4*)&g_h[ro + 4] = make_float4(acc[i][4], acc[i][5], acc[i][6], acc[i][7]);
    }
}

// ---------------- K3b: suffix scans A1/A2 per (b,c) ----------------
__global__ __launch_bounds__(1024) void k_scan(void) {
    __shared__ float a1[1024];
    __shared__ float a2[1024];
    int c = blockIdx.x, b = blockIdx.y, j = threadIdx.x;
    int p = g_perm[b * 1024 + j];
    float sps = g_sp_sorted[b * 1024 + j];
    float hv = g_h[((size_t)(b * 256 + c) << 10) + p];
    a1[j] = hv;
    a2[j] = sps * hv;
    __syncthreads();
    for (int s = 1; s < 1024; s <<= 1) {
        float t1 = a1[j] + ((j + s < 1024) ? a1[j + s] : 0.f);
        float t2 = a2[j] + ((j + s < 1024) ? a2[j + s] : 0.f);
        __syncthreads();
        a1[j] = t1; a2[j] = t2;
        __syncthreads();
    }
    size_t base = (size_t)(b * 256 + c) * MP1;
    g_A1[base + j] = a1[j];
    g_A2[base + j] = a2[j];
    if (j == 0) { g_A1[base + 1024] = 0.f; g_A2[base + 1024] = 0.f; }
}

// ---------------- K5: BN statistics (one block per channel) ----------------
__global__ __launch_bounds__(256) void k_bnstats(const float* __restrict__ W_b,
                                                 const float* __restrict__ gamma,
                                                 const float* __restrict__ beta) {
    int c = blockIdx.x, tid = threadIdx.x;
    __shared__ float A1s[MP1], A2s[MP1];
    __shared__ double rs[256], rq[256];
    double sum = 0.0, sq = 0.0;
    float wb = W_b[c];
    const float invM = 1.0f / 1024.0f;
    for (int b = 0; b < 8; b++) {
        size_t base = (size_t)(b * 256 + c) * MP1;
        for (int i = tid; i < MP1; i += 256) { A1s[i] = g_A1[base + i]; A2s[i] = g_A2[base + i]; }
        __syncthreads();
        for (int n = tid; n < 4096; n += 256) {
            float st = g_st[b * 4096 + n];
            int kk = g_kidx[b * 4096 + n];
            float val = (st * A1s[kk] + A2s[kk]) * invM + wb;
            sum += (double)val;
            sq  += (double)val * (double)val;
        }
        __syncthreads();
    }
    rs[tid] = sum; rq[tid] = sq;
    __syncthreads();
    for (int s = 128; s > 0; s >>= 1) {
        if (tid < s) { rs[tid] += rs[tid + s]; rq[tid] += rq[tid + s]; }
        __syncthreads();
    }
    if (tid == 0) {
        double mean = rs[0] / 32768.0;
        double var  = rq[0] / 32768.0 - mean * mean;
        float rstd = rsqrtf((float)var + 1e-5f);
        float sc = gamma[c] * rstd;
        g_scale[c] = sc;
        g_shift[c] = beta[c] - (float)mean * sc;
    }
}

// ---------------- K6: normalize + residual ----------------
__global__ __launch_bounds__(256) void k_final(const float* __restrict__ x,
                                               const float* __restrict__ W_b,
                                               float* __restrict__ out) {
    int c = blockIdx.x, b = blockIdx.y, tid = threadIdx.x;
    __shared__ float A1s[MP1], A2s[MP1];
    size_t base = (size_t)(b * 256 + c) * MP1;
    for (int i = tid; i < MP1; i += 256) { A1s[i] = g_A1[base + i]; A2s[i] = g_A2[base + i]; }
    __syncthreads();
    float wb = W_b[c], sc = g_scale[c], sh = g_shift[c];
    const float invM = 1.0f / 1024.0f;
    size_t xo = ((size_t)b * 256 + c) * 4096;
    for (int n = tid; n < 4096; n += 256) {
        float st = g_st[b * 4096 + n];
        int kk = g_kidx[b * 4096 + n];
        float val = (st * A1s[kk] + A2s[kk]) * invM + wb;
        out[xo + n] = val * sc + sh + x[xo + n];
    }
}

// ---------------- launch ----------------
extern "C" void kernel_launch(void* const* d_in, const int* in_sizes, int n_in,
                              void* d_out, int out_size) {
    const float* x       = (const float*)d_in[0];
    const float* g_w     = (const float*)d_in[1];
    const float* g_b     = (const float*)d_in[2];
    const float* theta_w = (const float*)d_in[3];
    const float* theta_b = (const float*)d_in[4];
    const float* phi_w   = (const float*)d_in[5];
    const float* phi_b   = (const float*)d_in[6];
    const float* cp_w    = (const float*)d_in[7];
    const float* W_w     = (const float*)d_in[8];
    const float* W_b     = (const float*)d_in[9];
    const float* bn_g    = (const float*)d_in[10];
    const float* bn_b    = (const float*)d_in[11];
    float* out = (float*)d_out;

    k_prep<<<256, 256>>>(g_w, g_b, phi_w, phi_b, theta_w, theta_b, cp_w);
    k_conv_gp<<<dim3(32, 2, 8), 256>>>(x, cp_w);
    k_st<<<dim3(16, 8), 256>>>(x);
    k_sort<<<8, 1024>>>();
    k_kidx<<<dim3(8, 8), 512>>>();
    k_wgemm<<<dim3(8, 2, 8), 256>>>(W_w);
    k_scan<<<dim3(256, 8), 1024>>>();
    k_bnstats<<<256, 256>>>(W_b, bn_g, bn_b);
    k_final<<<dim3(256, 8), 256>>>(x, W_b, out);
}

// round 17
// speedup vs baseline: 1.0336x; 1.0336x over previous
#include <cuda_runtime.h>
#include <cuda_bf16.h>
#include <mma.h>
#include <cstdint>

using namespace nvcuda;

// Problem constants: B=8, C=256, IC=128, H=W=64, N=4096, M=1024
#define NB   8
#define NC   256
#define NIC  128
#define NPIX 4096
#define NM   1024
#define MP1  1025

// ---------------- device scratch ----------------
// W pre-split: [rt][split][m 128][k 256] row-major bf16
__device__ __nv_bfloat16 g_Wimg[4 * 32768];
__device__ float g_bstack[256];
__device__ float g_vt[256];
__device__ float g_ct[1];
__device__ float g_gpool[NB * NIC * NM];
__device__ float g_sp[NB * NM];
__device__ float g_sp_sorted[NB * NM];
__device__ int   g_perm[NB * NM];
__device__ float g_st[NB * NPIX];
__device__ int   g_kidx[NB * NPIX];
__device__ float g_h[NB * NC * NM];
__device__ float g_A1[NB * NC * MP1];
__device__ float g_A2[NB * NC * MP1];
__device__ float g_scale[256];
__device__ float g_shift[256];

// ---------------- K0: biases, vt/ct, pre-split W images ----------------
__global__ void k_prep(const float* __restrict__ g_w, const float* __restrict__ g_b,
                       const float* __restrict__ phi_w, const float* __restrict__ phi_b,
                       const float* __restrict__ theta_w, const float* __restrict__ theta_b,
                       const float* __restrict__ cp_w) {
    int idx = blockIdx.x * 256 + threadIdx.x;   // 65536 W elements
    int r = idx >> 8, c = idx & 255;
    float w = (r < 128) ? g_w[r * 256 + c] : phi_w[(r - 128) * 256 + c];
    int rt = r >> 7, m = r & 127;
    __nv_bfloat16 hi = __float2bfloat16(w);
    __nv_bfloat16 lo = __float2bfloat16(w - __bfloat162float(hi));
    g_Wimg[(rt * 2 + 0) * 32768 + m * 256 + c] = hi;
    g_Wimg[(rt * 2 + 1) * 32768 + m * 256 + c] = lo;
    if (blockIdx.x == 0) {
        int t = threadIdx.x;
        g_bstack[t] = (t < 128) ? g_b[t] : phi_b[t - 128];
        float acc = 0.f;
        #pragma unroll 4
        for (int ic = 0; ic < 128; ic++) acc += cp_w[ic] * theta_w[ic * 256 + t];
        g_vt[t] = acc;
        if (t == 0) {
            float ct = 0.f;
            for (int ic = 0; ic < 128; ic++) ct += cp_w[ic] * theta_b[ic];
            g_ct[0] = ct;
        }
    }
}

// ---------------- K1: wmma split-bf16 stacked conv + fused maxpool ----------------
// Per CTA: D[128 ch, 128 pix] = W[128,256] @ x[256, tile 128]; K in 4 chunks of 64.
// smem: AH[128][72] AL[128][72] bf16 (18432 B each), BH[64][136] BL[64][136] bf16 (17408 B each)
#define LDA 72
#define LDB 136
#define LDD 132
#define OFF_AH 0
#define OFF_AL 18432
#define OFF_BH 36864
#define OFF_BL 54272
#define CONV_SMEM 71680

__global__ __launch_bounds__(256) void k_conv_tc(const float* __restrict__ x,
                                                 const float* __restrict__ cp_w) {
    extern __shared__ char sm[];
    const int t  = blockIdx.x;   // pooled row tile (128 pixels = img rows 2t,2t+1)
    const int rt = blockIdx.y;   // 0: g, 1: phi
    const int b  = blockIdx.z;
    const int tid = threadIdx.x;
    const int wid = tid >> 5;
    const int wm = wid >> 2;     // 0..1 -> m offset wm*64
    const int wn = wid & 3;      // 0..3 -> n offset wn*32

    __nv_bfloat16* AH = (__nv_bfloat16*)(sm + OFF_AH);
    __nv_bfloat16* AL = (__nv_bfloat16*)(sm + OFF_AL);
    __nv_bfloat16* BH = (__nv_bfloat16*)(sm + OFF_BH);
    __nv_bfloat16* BL = (__nv_bfloat16*)(sm + OFF_BL);

    wmma::fragment<wmma::accumulator, 16, 16, 16, float> acc[4][2];
    #pragma unroll
    for (int mf = 0; mf < 4; mf++)
        #pragma unroll
        for (int nf = 0; nf < 2; nf++) wmma::fill_fragment(acc[mf][nf], 0.f);

    const float* xb0 = x + (size_t)b * 256 * 4096 + t * 128;
    const __nv_bfloat16* Wh = g_Wimg + (size_t)(rt * 2 + 0) * 32768;
    const __nv_bfloat16* Wl = g_Wimg + (size_t)(rt * 2 + 1) * 32768;

    #pragma unroll 1
    for (int chunk = 0; chunk < 4; chunk++) {
        // A copy: 128 rows x 64 cols bf16, both splits (1024 uint4 each)
        #pragma unroll
        for (int i = 0; i < 4; i++) {
            int c = tid + i * 256;
            int row = c >> 3, cu = (c & 7) * 8;
            int so = row * 256 + chunk * 64 + cu;
            int dofs = row * LDA + cu;
            *(uint4*)(AH + dofs) = *(const uint4*)(Wh + so);
            *(uint4*)(AL + dofs) = *(const uint4*)(Wl + so);
        }
        // B convert: x[chunk*64 + k][n] -> bf16 hi/lo, row-major [k][n]
        #pragma unroll 4
        for (int i = 0; i < 32; i++) {
            int e = i * 256 + tid;
            int n = e & 127, k = e >> 7;
            float v = xb0[(size_t)(chunk * 64 + k) * 4096 + n];
            __nv_bfloat16 h = __float2bfloat16(v);
            __nv_bfloat16 l = __float2bfloat16(v - __bfloat162float(h));
            BH[k * LDB + n] = h;
            BL[k * LDB + n] = l;
        }
        __syncthreads();

        #pragma unroll
        for (int kf = 0; kf < 4; kf++) {
            wmma::fragment<wmma::matrix_b, 16, 16, 16, __nv_bfloat16, wmma::row_major> bh[2], bl[2];
            #pragma unroll
            for (int nf = 0; nf < 2; nf++) {
                int bo = kf * 16 * LDB + wn * 32 + nf * 16;
                wmma::load_matrix_sync(bh[nf], BH + bo, LDB);
                wmma::load_matrix_sync(bl[nf], BL + bo, LDB);
            }
            #pragma unroll
            for (int mf = 0; mf < 4; mf++) {
                wmma::fragment<wmma::matrix_a, 16, 16, 16, __nv_bfloat16, wmma::row_major> ah, al;
                int ao = (wm * 64 + mf * 16) * LDA + kf * 16;
                wmma::load_matrix_sync(ah, AH + ao, LDA);
                wmma::load_matrix_sync(al, AL + ao, LDA);
                #pragma unroll
                for (int nf = 0; nf < 2; nf++) {
                    wmma::mma_sync(acc[mf][nf], ah, bh[nf], acc[mf][nf]);
                    wmma::mma_sync(acc[mf][nf], ah, bl[nf], acc[mf][nf]);
                    wmma::mma_sync(acc[mf][nf], al, bh[nf], acc[mf][nf]);
                }
            }
        }
        __syncthreads();
    }

    // Store D to smem fp32 [128][LDD]
    float* Dsm = (float*)sm;
    #pragma unroll
    for (int mf = 0; mf < 4; mf++)
        #pragma unroll
        for (int nf = 0; nf < 2; nf++)
            wmma::store_matrix_sync(Dsm + (wm * 64 + mf * 16) * LDD + wn * 32 + nf * 16,
                                    acc[mf][nf], LDD, wmma::mem_row_major);
    __syncthreads();

    // Epilogue: maxpool 2x2. Thread -> ch = tid&127, half = tid>>7 (mw 16 each)
    const int ch = tid & 127;
    const int half = tid >> 7;
    float bias = g_bstack[rt * 128 + ch];
    float pl[16];
    #pragma unroll
    for (int q = 0; q < 16; q++) {
        int mw = half * 16 + q;
        float a0 = Dsm[ch * LDD + 2 * mw];
        float a1 = Dsm[ch * LDD + 2 * mw + 1];
        float a2 = Dsm[ch * LDD + 64 + 2 * mw];
        float a3 = Dsm[ch * LDD + 64 + 2 * mw + 1];
        pl[q] = fmaxf(fmaxf(a0, a1), fmaxf(a2, a3)) + bias;
    }
    __syncthreads();   // done reading Dsm before any reuse

    if (rt == 0) {
        float* dst = g_gpool + (((size_t)(b * 128 + ch)) << 10) + t * 32 + half * 16;
        #pragma unroll
        for (int q = 0; q < 4; q++)
            *(float4*)(dst + q * 4) = make_float4(pl[4 * q], pl[4 * q + 1], pl[4 * q + 2], pl[4 * q + 3]);
    } else {
        float wp = cp_w[128 + ch];
        float* red = (float*)sm;   // [32 mw][128 ch]
        #pragma unroll
        for (int q = 0; q < 16; q++) red[(half * 16 + q) * 128 + ch] = wp * pl[q];
        __syncthreads();
        if (tid < 32) {
            float s = 0.f;
            #pragma unroll 8
            for (int cc = 0; cc < 128; cc++) s += red[tid * 128 + cc];
            g_sp[b * 1024 + t * 32 + tid] = s;
        }
    }
}

// ---------------- K2: s_t ----------------
__global__ __launch_bounds__(256) void k_st(const float* __restrict__ x) {
    __shared__ float vts[256];
    int tid = threadIdx.x;
    vts[tid] = g_vt[tid];
    __syncthreads();
    int b = blockIdx.y;
    int n = blockIdx.x * 256 + tid;
    const float* xb = x + (size_t)b * 256 * 4096 + n;
    float a0 = 0.f, a1 = 0.f, a2 = 0.f, a3 = 0.f;
    #pragma unroll 4
    for (int c = 0; c < 256; c += 4) {
        a0 += vts[c + 0] * xb[(size_t)(c + 0) * 4096];
        a1 += vts[c + 1] * xb[(size_t)(c + 1) * 4096];
        a2 += vts[c + 2] * xb[(size_t)(c + 2) * 4096];
        a3 += vts[c + 3] * xb[(size_t)(c + 3) * 4096];
    }
    g_st[b * 4096 + n] = (a0 + a1) + (a2 + a3) + g_ct[0];
}

// ---------------- K3a: bitonic sort ----------------
__global__ __launch_bounds__(1024) void k_sort(void) {
    __shared__ float key[1024];
    __shared__ int   idx[1024];
    int b = blockIdx.x, tid = threadIdx.x;
    key[tid] = g_sp[b * 1024 + tid];
    idx[tid] = tid;
    __syncthreads();
    for (int k = 2; k <= 1024; k <<= 1) {
        for (int j = k >> 1; j > 0; j >>= 1) {
            int ixj = tid ^ j;
            if (ixj > tid) {
                bool up = ((tid & k) == 0);
                float a = key[tid], bb = key[ixj];
                bool sw = up ? (a > bb) : (a < bb);
                if (sw) {
                    key[tid] = bb; key[ixj] = a;
                    int ti = idx[tid]; idx[tid] = idx[ixj]; idx[ixj] = ti;
                }
            }
            __syncthreads();
        }
    }
    g_sp_sorted[b * 1024 + tid] = key[tid];
    g_perm[b * 1024 + tid] = idx[tid];
}

// ---------------- K3c: k-index binary search ----------------
__global__ __launch_bounds__(512) void k_kidx(void) {
    __shared__ float sp[1024];
    int b = blockIdx.y, tid = threadIdx.x;
    for (int i = tid; i < 1024; i += 512) sp[i] = g_sp_sorted[b * 1024 + i];
    __syncthreads();
    int n = blockIdx.x * 512 + tid;
    float tv = -g_st[b * 4096 + n];
    int lo = 0, hi = 1024;
    #pragma unroll
    for (int it = 0; it < 10; it++) {
        int mid = (lo + hi) >> 1;
        if (sp[mid] <= tv) lo = mid + 1; else hi = mid;
    }
    g_kidx[b * 4096 + n] = lo;
}

// ---------------- K4: h = W_w @ g_pool ----------------
__global__ __launch_bounds__(256) void k_wgemm(const float* __restrict__ W_w) {
    const int t  = blockIdx.x;
    const int rt = blockIdx.y;
    const int b  = blockIdx.z;
    __shared__ float As[2][16][128];
    __shared__ float Bs[2][16][128];
    const int tid = threadIdx.x;
    const int tx = tid & 15, ty = tid >> 4;
    const float* Aw = W_w + rt * 128 * 128;
    const float* Bg = g_gpool + (size_t)b * 128 * 1024 + t * 128;

    float acc[8][8];
    #pragma unroll
    for (int i = 0; i < 8; i++)
        #pragma unroll
        for (int j = 0; j < 8; j++) acc[i][j] = 0.f;

    #pragma unroll
    for (int r = 0; r < 2; r++) {
        int id = tid + r * 256;
        int m = id >> 2, kq = id & 3;
        float4 v = *(const float4*)(Aw + m * 128 + kq * 4);
        As[0][kq * 4 + 0][m] = v.x; As[0][kq * 4 + 1][m] = v.y;
        As[0][kq * 4 + 2][m] = v.z; As[0][kq * 4 + 3][m] = v.w;
        int kb = id >> 5, nq = id & 31;
        *(float4*)&Bs[0][kb][nq * 4] = *(const float4*)(Bg + (size_t)kb * 1024 + nq * 4);
    }
    __syncthreads();

    #pragma unroll 1
    for (int ks = 0; ks < 8; ks++) {
        int buf = ks & 1;
        if (ks < 7) {
            int k0 = (ks + 1) * 16;
            #pragma unroll
            for (int r = 0; r < 2; r++) {
                int id = tid + r * 256;
                int m = id >> 2, kq = id & 3;
                float4 v = *(const float4*)(Aw + m * 128 + k0 + kq * 4);
                As[buf ^ 1][kq * 4 + 0][m] = v.x; As[buf ^ 1][kq * 4 + 1][m] = v.y;
                As[buf ^ 1][kq * 4 + 2][m] = v.z; As[buf ^ 1][kq * 4 + 3][m] = v.w;
                int kb = id >> 5, nq = id & 31;
                *(float4*)&Bs[buf ^ 1][kb][nq * 4] =
                    *(const float4*)(Bg + (size_t)(k0 + kb) * 1024 + nq * 4);
            }
        }
        #pragma unroll
        for (int kk = 0; kk < 16; kk++) {
            float a[8], bb[8];
            *(float4*)&a[0]  = *(const float4*)&As[buf][kk][ty * 8];
            *(float4*)&a[4]  = *(const float4*)&As[buf][kk][ty * 8 + 4];
            *(float4*)&bb[0] = *(const float4*)&Bs[buf][kk][tx * 8];
            *(float4*)&bb[4] = *(const float4*)&Bs[buf][kk][tx * 8 + 4];
            #pragma unroll
            for (int i = 0; i < 8; i++)
                #pragma unroll
                for (int j = 0; j < 8; j++) acc[i][j] += a[i] * bb[j];
        }
        __syncthreads();
    }

    #pragma unroll
    for (int i = 0; i < 8; i++) {
        size_t ro = ((size_t)(b * 256 + rt * 128 + ty * 8 + i) << 10) + t * 128 + tx * 8;
        *(float4*)&g_h[ro]     = make_float4(acc[i][0], acc[i][1], acc[i][2], acc[i][3]);
        *(float4*)&g_h[ro + 4] = make_float4(acc[i][4], acc[i][5], acc[i][6], acc[i][7]);
    }
}

// ---------------- K3b: suffix scans ----------------
__global__ __launch_bounds__(1024) void k_scan(void) {
    __shared__ float a1[1024];
    __shared__ float a2[1024];
    int c = blockIdx.x, b = blockIdx.y, j = threadIdx.x;
    int p = g_perm[b * 1024 + j];
    float sps = g_sp_sorted[b * 1024 + j];
    float hv = g_h[((size_t)(b * 256 + c) << 10) + p];
    a1[j] = hv;
    a2[j] = sps * hv;
    __syncthreads();
    for (int s = 1; s < 1024; s <<= 1) {
        float t1 = a1[j] + ((j + s < 1024) ? a1[j + s] : 0.f);
        float t2 = a2[j] + ((j + s < 1024) ? a2[j + s] : 0.f);
        __syncthreads();
        a1[j] = t1; a2[j] = t2;
        __syncthreads();
    }
    size_t base = (size_t)(b * 256 + c) * MP1;
    g_A1[base + j] = a1[j];
    g_A2[base + j] = a2[j];
    if (j == 0) { g_A1[base + 1024] = 0.f; g_A2[base + 1024] = 0.f; }
}

// ---------------- K5: BN stats ----------------
__global__ __launch_bounds__(256) void k_bnstats(const float* __restrict__ W_b,
                                                 const float* __restrict__ gamma,
                                                 const float* __restrict__ beta) {
    int c = blockIdx.x, tid = threadIdx.x;
    __shared__ float A1s[MP1], A2s[MP1];
    __shared__ double rs[256], rq[256];
    double sum = 0.0, sq = 0.0;
    float wb = W_b[c];
    const float invM = 1.0f / 1024.0f;
    for (int b = 0; b < 8; b++) {
        size_t base = (size_t)(b * 256 + c) * MP1;
        for (int i = tid; i < MP1; i += 256) { A1s[i] = g_A1[base + i]; A2s[i] = g_A2[base + i]; }
        __syncthreads();
        for (int n = tid; n < 4096; n += 256) {
            float st = g_st[b * 4096 + n];
            int kk = g_kidx[b * 4096 + n];
            float val = (st * A1s[kk] + A2s[kk]) * invM + wb;
            sum += (double)val;
            sq  += (double)val * (double)val;
        }
        __syncthreads();
    }
    rs[tid] = sum; rq[tid] = sq;
    __syncthreads();
    for (int s = 128; s > 0; s >>= 1) {
        if (tid < s) { rs[tid] += rs[tid + s]; rq[tid] += rq[tid + s]; }
        __syncthreads();
    }
    if (tid == 0) {
        double mean = rs[0] / 32768.0;
        double var  = rq[0] / 32768.0 - mean * mean;
        float rstd = rsqrtf((float)var + 1e-5f);
        float sc = gamma[c] * rstd;
        g_scale[c] = sc;
        g_shift[c] = beta[c] - (float)mean * sc;
    }
}

// ---------------- K6: normalize + residual ----------------
__global__ __launch_bounds__(256) void k_final(const float* __restrict__ x,
                                               const float* __restrict__ W_b,
                                               float* __restrict__ out) {
    int c = blockIdx.x, b = blockIdx.y, tid = threadIdx.x;
    __shared__ float A1s[MP1], A2s[MP1];
    size_t base = (size_t)(b * 256 + c) * MP1;
    for (int i = tid; i < MP1; i += 256) { A1s[i] = g_A1[base + i]; A2s[i] = g_A2[base + i]; }
    __syncthreads();
    float wb = W_b[c], sc = g_scale[c], sh = g_shift[c];
    const float invM = 1.0f / 1024.0f;
    size_t xo = ((size_t)b * 256 + c) * 4096;
    for (int n = tid; n < 4096; n += 256) {
        float st = g_st[b * 4096 + n];
        int kk = g_kidx[b * 4096 + n];
        float val = (st * A1s[kk] + A2s[kk]) * invM + wb;
        out[xo + n] = val * sc + sh + x[xo + n];
    }
}

// ---------------- launch ----------------
extern "C" void kernel_launch(void* const* d_in, const int* in_sizes, int n_in,
                              void* d_out, int out_size) {
    const float* x       = (const float*)d_in[0];
    const float* g_w     = (const float*)d_in[1];
    const float* g_b     = (const float*)d_in[2];
    const float* theta_w = (const float*)d_in[3];
    const float* theta_b = (const float*)d_in[4];
    const float* phi_w   = (const float*)d_in[5];
    const float* phi_b   = (const float*)d_in[6];
    const float* cp_w    = (const float*)d_in[7];
    const float* W_w     = (const float*)d_in[8];
    const float* W_b     = (const float*)d_in[9];
    const float* bn_g    = (const float*)d_in[10];
    const float* bn_b    = (const float*)d_in[11];
    float* out = (float*)d_out;

    cudaFuncSetAttribute(k_conv_tc, cudaFuncAttributeMaxDynamicSharedMemorySize, CONV_SMEM);

    k_prep<<<256, 256>>>(g_w, g_b, phi_w, phi_b, theta_w, theta_b, cp_w);
    k_conv_tc<<<dim3(32, 2, 8), 256, CONV_SMEM>>>(x, cp_w);
    k_st<<<dim3(16, 8), 256>>>(x);
    k_sort<<<8, 1024>>>();
    k_kidx<<<dim3(8, 8), 512>>>();
    k_wgemm<<<dim3(8, 2, 8), 256>>>(W_w);
    k_scan<<<dim3(256, 8), 1024>>>();
    k_bnstats<<<256, 256>>>(W_b, bn_g, bn_b);
    k_final<<<dim3(256, 8), 256>>>(x, W_b, out);
}